// round 3
// baseline (speedup 1.0000x reference)
#include <cuda_runtime.h>

#define N_FFT    800
#define HOP      200
#define BATCH    32
#define TLEN     480000
#define PAD      400
#define N_FRAMES 2401          // (480800 - 800)/200 + 1
#define FPB      16            // frames per block in frame_sums

#define PI_D 3.14159265358979323846

// Scratch: per-(batch,frame) even/odd windowed sums, plus the window table.
__device__ float g_win[N_FFT];
__device__ float g_S[BATCH][N_FRAMES][2];

__global__ void init_window_kernel() {
    int i = blockIdx.x * blockDim.x + threadIdx.x;
    if (i < N_FFT) {
        double w = 0.5 - 0.5 * cos(2.0 * PI_D * (double)i / (double)N_FFT);
        g_win[i] = (float)w;
    }
}

// Kernel 1: for each (b, f) compute Se = sum over even n of win[n]*xp[f*HOP+n],
// So = sum over odd n. Edge-padded input handled by index clamping.
// Block covers FPB consecutive frames of one batch; overlapping samples are
// staged once in shared memory (span = FPB*HOP + (N_FFT-HOP) = 3800 floats).
__global__ __launch_bounds__(FPB * 32) void frame_sums_kernel(const float* __restrict__ x) {
    __shared__ float sx[FPB * HOP + (N_FFT - HOP)];   // 3800 floats = 15.2 KB
    const int b  = blockIdx.y;
    const int f0 = blockIdx.x * FPB;
    const float* xb = x + (size_t)b * TLEN;
    const int base = f0 * HOP - PAD;                   // x-coordinate of sx[0]
    const int span = FPB * HOP + (N_FFT - HOP);

    for (int i = threadIdx.x; i < span; i += blockDim.x) {
        int idx = base + i;
        idx = idx < 0 ? 0 : (idx >= TLEN ? TLEN - 1 : idx);
        sx[i] = xb[idx];
    }
    __syncthreads();

    const int w = threadIdx.x >> 5;
    const int l = threadIdx.x & 31;
    const int f = f0 + w;
    if (f < N_FRAMES) {
        // Lane l touches n = l, l+32, ... -> fixed parity = l & 1.
        float s = 0.0f;
        #pragma unroll
        for (int k = 0; k < N_FFT / 32; k++) {
            const int m = l + 32 * k;
            s = fmaf(g_win[m], sx[w * HOP + m], s);
        }
        // Sum across lanes of identical parity (bit 0 preserved by xor 2/4/8/16).
        s += __shfl_xor_sync(0xffffffffu, s, 2);
        s += __shfl_xor_sync(0xffffffffu, s, 4);
        s += __shfl_xor_sync(0xffffffffu, s, 8);
        s += __shfl_xor_sync(0xffffffffu, s, 16);
        if (l < 2) g_S[b][f][l] = s;   // lane0 -> Se, lane1 -> So
    }
}

// Kernel 2: overlap-add synthesis.
// Output sample t (xp coord tp = t + PAD) receives contributions from frames
// f = q..q-3 (q = tp/HOP), each at in-frame offset n = r + 200*j (r = tp%HOP).
// All four contributions read the SAME input sample xp[tp] = x[t]:
//   out[t] = ( 400 * x[t] * sum_j win^2(n_j)  +  sum_j win(n_j)*S_par[f_j] ) / 800
// Window quadruple from one sincos: win(r)=0.5-0.5c, win(r+200)=0.5+0.5s,
// win(r+400)=0.5+0.5c, win(r+600)=0.5-0.5s with (s,c)=sincos(pi*r/400).
__global__ __launch_bounds__(256) void synth_kernel(const float* __restrict__ x,
                                                    float* __restrict__ out) {
    const int gid = blockIdx.x * blockDim.x + threadIdx.x;
    if (gid >= BATCH * TLEN) return;
    const int b  = gid / TLEN;
    const int t  = gid - b * TLEN;
    const int tp = t + PAD;
    const int q  = tp / HOP;
    const int r  = tp - q * HOP;
    const int par = tp & 1;

    float s, c;
    __sincosf((float)r * (float)(PI_D / 400.0), &s, &c);
    float wv[4];
    wv[0] = 0.5f - 0.5f * c;
    wv[1] = 0.5f + 0.5f * s;
    wv[2] = 0.5f + 0.5f * c;
    wv[3] = 0.5f - 0.5f * s;

    const float xv = x[gid];
    float acc = 0.0f, wsq = 0.0f;
    #pragma unroll
    for (int j = 0; j < 4; j++) {
        const int f = q - j;
        if (f >= 0 && f < N_FRAMES) {
            wsq = fmaf(wv[j], wv[j], wsq);
            acc = fmaf(wv[j], g_S[b][f][par], acc);
        }
    }
    out[gid] = fmaf(400.0f * wsq, xv, acc) * (1.0f / 800.0f);
}

extern "C" void kernel_launch(void* const* d_in, const int* in_sizes, int n_in,
                              void* d_out, int out_size) {
    const float* x = (const float*)d_in[0];
    float* out = (float*)d_out;

    init_window_kernel<<<1, N_FFT>>>();

    dim3 grid1((N_FRAMES + FPB - 1) / FPB, BATCH);
    frame_sums_kernel<<<grid1, FPB * 32>>>(x);

    const int total = BATCH * TLEN;
    synth_kernel<<<(total + 255) / 256, 256>>>(x, out);
}

// round 5
// speedup vs baseline: 1.2663x; 1.2663x over previous
#include <cuda_runtime.h>

#define N_FFT    800
#define HOP      200
#define BATCH    32
#define TLEN     480000
#define PAD      400
#define N_FRAMES 2401                 // (480800 - 800)/200 + 1
#define TS       8000                 // output tile per block (multiple of HOP)
#define NF_LOC   (TS / HOP + 3)       // 43 frames overlap a tile
#define SPAN     (TS + 1200)          // staged input span: [t0-600, t0+TS+600)

#define PI_D 3.14159265358979323846

// Fully fused STFT->mag/phase->iSTFT.
//
// Math: rp==real, ip==imag up to sqrt(1+1e-14/h^2) (<1e-9 rel), so the whole
// pipeline is linear with kernel M[n,m] = win[n]win[m]/800 * (1 + 400*[n==m] ... )
// via Dirichlet collapse of sum_{k=0..400} cos(2pi k (n-m)/800) =
//   401 if n==m, 1 if (n-m) even, 0 if odd.  Hence per frame f:
//   y_f[n] = win[n]/800 * (400*win[n]*xp_f[n] + S_{parity(n)}[f]),
// where Se/So[f] = sum over even/odd m of win[m]*xp_f[m].
// Overlap-add of 4 frames at output tp, with n_j = r + 200j (r = tp%200),
// all reading the SAME input sample x[t]:
//   out[t] = ( 400*x[t]*sum_j win(n_j)^2 + sum_j win(n_j)*S_par[f_j] ) / 800.
__global__ __launch_bounds__(1024, 2)
void stft_fused_kernel(const float* __restrict__ x, float* __restrict__ out) {
    __shared__ float sx[SPAN];          // staged (clamped) input
    __shared__ float sw[N_FFT];         // Hann window
    __shared__ float sS[NF_LOC][2];     // per-local-frame even/odd windowed sums

    const int b  = blockIdx.y;
    const int t0 = blockIdx.x * TS;
    const float* xb = x + (size_t)b * TLEN;
    const int base = t0 - 600;          // x-coordinate of sx[0]

    // Window table (replaces the separate double-precision init kernel).
    for (int i = threadIdx.x; i < N_FFT; i += blockDim.x)
        sw[i] = 0.5f - 0.5f * cosf((float)i * (float)(2.0 * PI_D / N_FFT));

    // Stage input. Interior tiles take the vectorized path (base mult of 4).
    if (base >= 0 && base + SPAN <= TLEN) {
        const float4* __restrict__ src = (const float4*)(xb + base);
        float4* dst = (float4*)sx;
        for (int i = threadIdx.x; i < SPAN / 4; i += blockDim.x)
            dst[i] = src[i];
    } else {
        for (int i = threadIdx.x; i < SPAN; i += blockDim.x) {
            int idx = base + i;
            idx = idx < 0 ? 0 : (idx >= TLEN ? TLEN - 1 : idx);
            sx[i] = xb[idx];
        }
    }
    __syncthreads();

    // Phase 1: frame parity sums, one warp per local frame.
    // Local frame fl = global frame (t0/HOP - 1 + fl); its window starts at
    // xp[f*HOP] = x[f*HOP-400] = sx[fl*HOP].
    const int w = threadIdx.x >> 5;
    const int l = threadIdx.x & 31;
    for (int fl = w; fl < NF_LOC; fl += 32) {
        float s = 0.0f;
        #pragma unroll
        for (int k = 0; k < N_FFT / 32; k++) {
            const int m = l + 32 * k;          // parity(m) == parity(l)
            s = fmaf(sw[m], sx[fl * HOP + m], s);
        }
        s += __shfl_xor_sync(0xffffffffu, s, 2);
        s += __shfl_xor_sync(0xffffffffu, s, 4);
        s += __shfl_xor_sync(0xffffffffu, s, 8);
        s += __shfl_xor_sync(0xffffffffu, s, 16);
        if (l < 2) sS[fl][l] = s;              // lane0 -> Se, lane1 -> So
    }
    __syncthreads();

    // Phase 2: overlap-add synthesis, entirely from smem (no MUFU).
    const int f_base = t0 / HOP - 1;
    float* __restrict__ ob = out + (size_t)b * TLEN + t0;
    for (int i = threadIdx.x; i < TS; i += blockDim.x) {
        const int tp  = t0 + i + PAD;
        const int q   = tp / HOP;
        const int r   = tp - q * HOP;
        const int par = tp & 1;
        const float xv = sx[i + 600];

        float acc = 0.0f, wsq = 0.0f;
        #pragma unroll
        for (int j = 0; j < 4; j++) {
            const int f = q - j;
            if (f >= 0 && f < N_FRAMES) {      // only first/last tiles ever fail
                const float wv = sw[r + HOP * j];
                wsq = fmaf(wv, wv, wsq);
                acc = fmaf(wv, sS[f - f_base][par], acc);
            }
        }
        ob[i] = fmaf(400.0f * wsq, xv, acc) * (1.0f / 800.0f);
    }
}

extern "C" void kernel_launch(void* const* d_in, const int* in_sizes, int n_in,
                              void* d_out, int out_size) {
    const float* x = (const float*)d_in[0];
    float* out = (float*)d_out;

    dim3 grid(TLEN / TS, BATCH);       // 60 x 32 = 1920 blocks
    stft_fused_kernel<<<grid, 1024>>>(x, out);
}

// round 6
// speedup vs baseline: 1.3345x; 1.0538x over previous
#include <cuda_runtime.h>

#define N_FFT    800
#define HOP      200
#define BATCH    32
#define TLEN     480000
#define PAD      400
#define N_FRAMES 2401                 // (480800 - 800)/200 + 1
#define TS       8000                 // output tile per block (multiple of HOP)
#define NF_LOC   (TS / HOP + 3)       // 43 frames overlap a tile
#define SPAN     (TS + 1200)          // staged input span: [t0-600, t0+TS+600)

#define PI_D 3.14159265358979323846

// Fully fused STFT->mag/phase->iSTFT (linear-collapse derivation, see R3).
//   out[t] = ( 400*x[t]*sum_j win(n_j)^2 + sum_j win(n_j)*S_par[f_j] ) / 800,
//   n_j = r + 200j, Se/So[f] = parity-split windowed frame sums.
__global__ __launch_bounds__(1024, 2)
void stft_fused_kernel(const float* __restrict__ x, float* __restrict__ out) {
    __shared__ __align__(16) float  sx[SPAN];     // staged (clamped) input
    __shared__ __align__(16) float  sw[N_FFT];    // Hann window
    __shared__ __align__(8)  float2 sS[NF_LOC];   // per-local-frame (Se, So)

    const int b  = blockIdx.y;
    const int t0 = blockIdx.x * TS;
    const float* xb = x + (size_t)b * TLEN;
    const int base = t0 - 600;          // x-coordinate of sx[0]
    const bool edge = (blockIdx.x == 0) | (blockIdx.x == gridDim.x - 1);

    // Window table.
    for (int i = threadIdx.x; i < N_FFT; i += blockDim.x)
        sw[i] = 0.5f - 0.5f * cosf((float)i * (float)(2.0 * PI_D / N_FFT));

    // Stage input (interior tiles: base is a multiple of 4 -> float4 path).
    if (!edge) {
        const float4* __restrict__ src = (const float4*)(xb + base);
        float4* dst = (float4*)sx;
        for (int i = threadIdx.x; i < SPAN / 4; i += blockDim.x)
            dst[i] = src[i];
    } else {
        for (int i = threadIdx.x; i < SPAN; i += blockDim.x) {
            int idx = base + i;
            idx = idx < 0 ? 0 : (idx >= TLEN ? TLEN - 1 : idx);
            sx[i] = xb[idx];
        }
    }
    __syncthreads();

    // Phase 1: frame parity sums, one warp per local frame, float4 loads.
    // float4 index f4 covers elements m=4*f4..4*f4+3; m parity fixed per slot.
    const int w = threadIdx.x >> 5;
    const int l = threadIdx.x & 31;
    const float4* __restrict__ sw4 = (const float4*)sw;
    for (int fl = w; fl < NF_LOC; fl += 32) {
        const float4* __restrict__ sx4 = (const float4*)&sx[fl * HOP];
        float se = 0.0f, so = 0.0f;
        #pragma unroll
        for (int k = 0; k < 7; k++) {
            const int f4 = l + 32 * k;
            if (f4 < N_FFT / 4) {              // only k=6 partially predicated
                const float4 wv = sw4[f4];
                const float4 xv = sx4[f4];
                se = fmaf(wv.x, xv.x, se); so = fmaf(wv.y, xv.y, so);
                se = fmaf(wv.z, xv.z, se); so = fmaf(wv.w, xv.w, so);
            }
        }
        #pragma unroll
        for (int d = 16; d >= 1; d >>= 1) {
            se += __shfl_xor_sync(0xffffffffu, se, d);
            so += __shfl_xor_sync(0xffffffffu, so, d);
        }
        if (l == 0) sS[fl] = make_float2(se, so);
    }
    __syncthreads();

    // Phase 2: overlap-add synthesis, 4 outputs per iteration.
    // tp = t0+4v+400 is a multiple of 4 -> r%4==0, r+3<200 so q is shared;
    // parity alternates (x,z even; y,w odd); sw quads are 16B-aligned.
    const int f_base = t0 / HOP - 1;
    float* __restrict__ ob = out + (size_t)b * TLEN + t0;
    if (!edge) {
        for (int v = threadIdx.x; v < TS / 4; v += blockDim.x) {
            const int i  = 4 * v;
            const int tp = t0 + i + PAD;
            const int q  = tp / HOP;
            const int r  = tp - q * HOP;
            const int flq = q - f_base;
            const float4 xv = *(const float4*)&sx[i + 600];
            float4 acc = make_float4(0.f, 0.f, 0.f, 0.f);
            float4 wsq = make_float4(0.f, 0.f, 0.f, 0.f);
            #pragma unroll
            for (int j = 0; j < 4; j++) {
                const float4 wv = *(const float4*)&sw[r + HOP * j];
                const float2 Sv = sS[flq - j];
                wsq.x = fmaf(wv.x, wv.x, wsq.x); acc.x = fmaf(wv.x, Sv.x, acc.x);
                wsq.y = fmaf(wv.y, wv.y, wsq.y); acc.y = fmaf(wv.y, Sv.y, acc.y);
                wsq.z = fmaf(wv.z, wv.z, wsq.z); acc.z = fmaf(wv.z, Sv.x, acc.z);
                wsq.w = fmaf(wv.w, wv.w, wsq.w); acc.w = fmaf(wv.w, Sv.y, acc.w);
            }
            float4 o;
            o.x = fmaf(400.0f * wsq.x, xv.x, acc.x) * (1.0f / 800.0f);
            o.y = fmaf(400.0f * wsq.y, xv.y, acc.y) * (1.0f / 800.0f);
            o.z = fmaf(400.0f * wsq.z, xv.z, acc.z) * (1.0f / 800.0f);
            o.w = fmaf(400.0f * wsq.w, xv.w, acc.w) * (1.0f / 800.0f);
            *(float4*)&ob[i] = o;
        }
    } else {
        for (int i = threadIdx.x; i < TS; i += blockDim.x) {
            const int tp  = t0 + i + PAD;
            const int q   = tp / HOP;
            const int r   = tp - q * HOP;
            const int par = tp & 1;
            const float xv = sx[i + 600];
            float acc = 0.0f, wsq = 0.0f;
            #pragma unroll
            for (int j = 0; j < 4; j++) {
                const int f = q - j;
                if (f >= 0 && f < N_FRAMES) {
                    const float wv = sw[r + HOP * j];
                    wsq = fmaf(wv, wv, wsq);
                    acc = fmaf(wv, par ? sS[f - f_base].y : sS[f - f_base].x, acc);
                }
            }
            ob[i] = fmaf(400.0f * wsq, xv, acc) * (1.0f / 800.0f);
        }
    }
}

extern "C" void kernel_launch(void* const* d_in, const int* in_sizes, int n_in,
                              void* d_out, int out_size) {
    const float* x = (const float*)d_in[0];
    float* out = (float*)d_out;

    dim3 grid(TLEN / TS, BATCH);       // 60 x 32 = 1920 blocks
    stft_fused_kernel<<<grid, 1024>>>(x, out);
}

// round 7
// speedup vs baseline: 1.8136x; 1.3590x over previous
#include <cuda_runtime.h>

#define N_FFT    800
#define HOP      200
#define BATCH    32
#define TLEN     480000
#define PAD      400
#define N_FRAMES 2401                 // (480800 - 800)/200 + 1
#define TS       8000                 // output tile per block
#define NF_LOC   (TS / HOP + 3)       // 43 frames overlap a tile
#define NBLK     (TS / HOP + 6)       // 46 hop blocks feed those frames
#define SPAN     (TS + 1200)          // staged input: [t0-600, t0+TS+600)

#define PI_D 3.14159265358979323846

// Fully fused STFT->mag/phase->iSTFT (linear-collapse derivation, R3).
// New identities (R6):
//   win(r+400) = 1-win(r), win(r+600) = 1-win(r+200)
//     -> per hop block g only X=sum(x), A=sum(win(r)x), B=sum(win(r+200)x)
//        and S[f] = A[f-2] + B[f-1] + (X[f]-A[f]) + (X[f+1]-B[f+1])
//   sum_j win(r+200j)^2 = 1.5 exactly
//     -> out = 0.75*x + (C0 + win(r)*C1 + win(r+200)*C2)/800,
//        C0=S[q-2]+S[q-3], C1=S[q]-S[q-2], C2=S[q-1]-S[q-3]  (per parity)
__global__ __launch_bounds__(1024, 2)
void stft_fused_kernel(const float* __restrict__ x, float* __restrict__ out) {
    __shared__ __align__(16) float sx[SPAN];        // staged (clamped) input
    __shared__ __align__(16) float sw[N_FFT];       // Hann window
    __shared__ float sX[NBLK][2], sA[NBLK][2], sB[NBLK][2];
    __shared__ float sS[NF_LOC][2];                 // frame parity sums
    __shared__ float sC0[NF_LOC + 1][2], sC1[NF_LOC + 1][2], sC2[NF_LOC + 1][2];

    const int b  = blockIdx.y;
    const int t0 = blockIdx.x * TS;
    const float* xb = x + (size_t)b * TLEN;
    const int base = t0 - 600;
    const bool edge = (blockIdx.x == 0) | (blockIdx.x == gridDim.x - 1);
    const int tid = threadIdx.x;

    // Window table.
    for (int i = tid; i < N_FFT; i += blockDim.x)
        sw[i] = 0.5f - 0.5f * cosf((float)i * (float)(2.0 * PI_D / N_FFT));

    // Stage input (interior: base is a multiple of 4 -> float4 path).
    if (!edge) {
        const float4* __restrict__ src = (const float4*)(xb + base);
        float4* dst = (float4*)sx;
        for (int i = tid; i < SPAN / 4; i += blockDim.x)
            dst[i] = src[i];
    } else {
        for (int i = tid; i < SPAN; i += blockDim.x) {
            int idx = base + i;
            idx = idx < 0 ? 0 : (idx >= TLEN ? TLEN - 1 : idx);
            sx[i] = xb[idx];
        }
    }
    __syncthreads();

    // Phase 1: per hop block g (200 samples at sx[200*gl]), three parity sums.
    // Each input sample touched ONCE. Lane l owns r = l+32k (parity fixed).
    const int w = tid >> 5;
    const int l = tid & 31;
    for (int gl = w; gl < NBLK; gl += 32) {
        const float* __restrict__ p = &sx[gl * HOP];
        float xs = 0.0f, as = 0.0f, bs = 0.0f;
        #pragma unroll
        for (int k = 0; k < 7; k++) {
            const int r = l + 32 * k;
            if (r < HOP) {
                const float v = p[r];
                xs += v;
                as = fmaf(sw[r], v, as);
                bs = fmaf(sw[r + HOP], v, bs);
            }
        }
        #pragma unroll
        for (int d = 16; d >= 2; d >>= 1) {     // keep bit0 (parity) intact
            xs += __shfl_xor_sync(0xffffffffu, xs, d);
            as += __shfl_xor_sync(0xffffffffu, as, d);
            bs += __shfl_xor_sync(0xffffffffu, bs, d);
        }
        if (l < 2) { sX[gl][l] = xs; sA[gl][l] = as; sB[gl][l] = bs; }
    }
    __syncthreads();

    // Phase 1.5: assemble frame sums S[fl] from X/A/B.
    if (tid < 2 * NF_LOC) {
        const int fl = tid >> 1, par = tid & 1;
        sS[fl][par] = sA[fl][par] + sB[fl + 1][par]
                    + (sX[fl + 2][par] - sA[fl + 2][par])
                    + (sX[fl + 3][par] - sB[fl + 3][par]);
    }
    __syncthreads();

    // Phase 1.75: per-frame-position combos for the interior synth.
    if (tid < 80) {                               // flq in [3, 43)
        const int flq = 3 + (tid >> 1), par = tid & 1;
        sC0[flq][par] = sS[flq - 2][par] + sS[flq - 3][par];
        sC1[flq][par] = sS[flq][par]     - sS[flq - 2][par];
        sC2[flq][par] = sS[flq - 1][par] - sS[flq - 3][par];
    }
    __syncthreads();

    // Phase 2: synthesis, 4 outputs per iteration.
    const int f_base = t0 / HOP - 1;
    float* __restrict__ ob = out + (size_t)b * TLEN + t0;
    if (!edge) {
        for (int v = tid; v < TS / 4; v += blockDim.x) {
            const int i   = 4 * v;
            const int tp0 = t0 + i + PAD;         // multiple of 4 -> shared q
            const int q   = tp0 / HOP;
            const int r0  = tp0 - q * HOP;        // mult of 4, <= 196
            const int flq = q - f_base;
            const float4 xv = ((const float4*)sx)[v + 150];
            const float4 w0 = *(const float4*)&sw[r0];
            const float4 w1 = *(const float4*)&sw[r0 + HOP];
            const float C0e = sC0[flq][0], C0o = sC0[flq][1];
            const float C1e = sC1[flq][0], C1o = sC1[flq][1];
            const float C2e = sC2[flq][0], C2o = sC2[flq][1];
            float4 o;   // parities: x,z even; y,w odd (tp0 even)
            o.x = fmaf(0.75f, xv.x, fmaf(w1.x, C2e, fmaf(w0.x, C1e, C0e)) * (1.0f / 800.0f));
            o.y = fmaf(0.75f, xv.y, fmaf(w1.y, C2o, fmaf(w0.y, C1o, C0o)) * (1.0f / 800.0f));
            o.z = fmaf(0.75f, xv.z, fmaf(w1.z, C2e, fmaf(w0.z, C1e, C0e)) * (1.0f / 800.0f));
            o.w = fmaf(0.75f, xv.w, fmaf(w1.w, C2o, fmaf(w0.w, C1o, C0o)) * (1.0f / 800.0f));
            *(float4*)&ob[i] = o;
        }
    } else {
        // Edge tiles: scalar path with frame-validity masking.
        for (int i = tid; i < TS; i += blockDim.x) {
            const int tp  = t0 + i + PAD;
            const int q   = tp / HOP;
            const int r   = tp - q * HOP;
            const int par = tp & 1;
            const float xv = sx[i + 600];
            float acc = 0.0f, wsq = 0.0f;
            #pragma unroll
            for (int j = 0; j < 4; j++) {
                const int f = q - j;
                if (f >= 0 && f < N_FRAMES) {
                    const float wv = sw[r + HOP * j];
                    wsq = fmaf(wv, wv, wsq);
                    acc = fmaf(wv, sS[f - f_base][par], acc);
                }
            }
            ob[i] = fmaf(400.0f * wsq, xv, acc) * (1.0f / 800.0f);
        }
    }
}

extern "C" void kernel_launch(void* const* d_in, const int* in_sizes, int n_in,
                              void* d_out, int out_size) {
    const float* x = (const float*)d_in[0];
    float* out = (float*)d_out;

    dim3 grid(TLEN / TS, BATCH);       // 60 x 32 = 1920 blocks
    stft_fused_kernel<<<grid, 1024>>>(x, out);
}